// round 9
// baseline (speedup 1.0000x reference)
#include <cuda_runtime.h>
#include <math.h>

#define D   256
#define NQ  512
#define NK  512

// ---------------- scratch ----------------
__device__ __align__(16) float g_aq[D * NQ];       // (d, n)
__device__ __align__(16) float g_ak[D * NK];       // (d, m)
__device__ __align__(16) float g_probT[NK * NQ];   // (m, n)
__device__ __align__(16) float g_msg[D * NQ];      // (d, n)
__device__ __align__(16) float g_h2pre[2 * D * NQ]; // wa[:, :256]@x + ba
__device__ __align__(16) float g_h2[2 * D * NQ];   // final h2

// ============ 2-way split-K core (KC=32, 256 thr) — for K=256 ============
// PRE: if pre != nullptr, epilogue adds pre[o][n] before activation.
template<int BM>
__device__ __forceinline__ void gemm2(
    const float* __restrict__ W, const float* __restrict__ X0,
    const float* __restrict__ bias, const float* __restrict__ pre,
    float* __restrict__ out, int K, bool relu)
{
    constexpr int TO = BM / 8;
    constexpr int WS = BM + 4;
    constexpr int NW = BM / 16;
    const int n0  = blockIdx.x * 64;
    const int o0  = blockIdx.y * BM;
    const int tid = threadIdx.x;
    const int wg  = tid >> 7;
    const int t   = tid & 127;
    const int nI  = t & 15;
    const int oG  = t >> 4;

    __shared__ __align__(16) float sW[2][32 * WS];
    __shared__ __align__(16) float sX[2][32 * 68];
    __shared__ __align__(16) float sR[128 * TO * 4];

    const int wo  = (BM == 32) ? (t >> 2) : (t >> 3);
    const int wf  = (BM == 32) ? (t & 3)  : (t & 7);
    const int xn4 = t & 15;
    const int xkr = t >> 4;

    const int kb  = wg * (K >> 1);
    const int NIT = K >> 6;

    float4 rw[NW], rx[4];
    float4 acc[TO];
    #pragma unroll
    for (int j = 0; j < TO; j++) acc[j] = make_float4(0.f, 0.f, 0.f, 0.f);

    {
        const int k0 = kb;
        #pragma unroll
        for (int p = 0; p < NW; p++)
            rw[p] = *(const float4*)&W[(o0 + wo) * 512 + k0 + (wf + p * 4) * 4];
        #pragma unroll
        for (int p = 0; p < 4; p++)
            rx[p] = *(const float4*)&X0[(k0 + xkr + p * 8) * 512 + n0 + xn4 * 4];
    }

    for (int it = 0; it < NIT; it++) {
        __syncthreads();
        #pragma unroll
        for (int p = 0; p < NW; p++) {
            const int f4 = wf + p * 4;
            sW[wg][(f4 * 4 + 0) * WS + wo] = rw[p].x;
            sW[wg][(f4 * 4 + 1) * WS + wo] = rw[p].y;
            sW[wg][(f4 * 4 + 2) * WS + wo] = rw[p].z;
            sW[wg][(f4 * 4 + 3) * WS + wo] = rw[p].w;
        }
        #pragma unroll
        for (int p = 0; p < 4; p++)
            *(float4*)&sX[wg][(xkr + p * 8) * 68 + xn4 * 4] = rx[p];
        __syncthreads();

        if (it + 1 < NIT) {
            const int k0 = kb + (it + 1) * 32;
            #pragma unroll
            for (int p = 0; p < NW; p++)
                rw[p] = *(const float4*)&W[(o0 + wo) * 512 + k0 + (wf + p * 4) * 4];
            #pragma unroll
            for (int p = 0; p < 4; p++)
                rx[p] = *(const float4*)&X0[(k0 + xkr + p * 8) * 512 + n0 + xn4 * 4];
        }

        #pragma unroll
        for (int k = 0; k < 32; k++) {
            float4 xv = *(const float4*)&sX[wg][k * 68 + nI * 4];
            if (TO == 4) {
                float4 wv = *(const float4*)&sW[wg][k * WS + oG * 4];
                acc[0].x += wv.x * xv.x; acc[0].y += wv.x * xv.y;
                acc[0].z += wv.x * xv.z; acc[0].w += wv.x * xv.w;
                acc[1].x += wv.y * xv.x; acc[1].y += wv.y * xv.y;
                acc[1].z += wv.y * xv.z; acc[1].w += wv.y * xv.w;
                acc[2].x += wv.z * xv.x; acc[2].y += wv.z * xv.y;
                acc[2].z += wv.z * xv.z; acc[2].w += wv.z * xv.w;
                acc[3].x += wv.w * xv.x; acc[3].y += wv.w * xv.y;
                acc[3].z += wv.w * xv.z; acc[3].w += wv.w * xv.w;
            } else {
                float2 wv = *(const float2*)&sW[wg][k * WS + oG * 2];
                acc[0].x += wv.x * xv.x; acc[0].y += wv.x * xv.y;
                acc[0].z += wv.x * xv.z; acc[0].w += wv.x * xv.w;
                acc[1].x += wv.y * xv.x; acc[1].y += wv.y * xv.y;
                acc[1].z += wv.y * xv.z; acc[1].w += wv.y * xv.w;
            }
        }
    }

    if (wg == 1) {
        #pragma unroll
        for (int j = 0; j < TO; j++)
            *(float4*)&sR[(t * TO + j) * 4] = acc[j];
    }
    __syncthreads();
    if (wg == 0) {
        #pragma unroll
        for (int j = 0; j < TO; j++) {
            float4 r = *(const float4*)&sR[(t * TO + j) * 4];
            const int o = o0 + oG * TO + j;
            const float b = bias ? bias[o] : 0.f;
            float4 v = acc[j];
            v.x += r.x + b; v.y += r.y + b; v.z += r.z + b; v.w += r.w + b;
            if (pre) {
                float4 pv = *(const float4*)&pre[o * 512 + n0 + nI * 4];
                v.x += pv.x; v.y += pv.y; v.z += pv.z; v.w += pv.w;
            }
            if (relu) {
                v.x = fmaxf(v.x, 0.f); v.y = fmaxf(v.y, 0.f);
                v.z = fmaxf(v.z, 0.f); v.w = fmaxf(v.w, 0.f);
            }
            *(float4*)&out[o * 512 + n0 + nI * 4] = v;
        }
    }
}

// ============ 4-way split-K core (KC=16, 512 thr) — for K=512 ============
template<int BM>
__device__ __forceinline__ void gemm4(
    const float* __restrict__ W, const float* __restrict__ X0,
    const float* __restrict__ bias, float* __restrict__ out, int K, bool relu)
{
    constexpr int TO = BM / 8;
    constexpr int WS = BM + 4;
    const int n0  = blockIdx.x * 64;
    const int o0  = blockIdx.y * BM;
    const int tid = threadIdx.x;
    const int wg  = tid >> 7;
    const int t   = tid & 127;
    const int nI  = t & 15;
    const int oG  = t >> 4;

    __shared__ __align__(16) float sW[4][16 * WS];
    __shared__ __align__(16) float sX[4][16 * 68];
    __shared__ __align__(16) float sR[2][128 * TO * 4];

    const int wo  = t >> 2;
    const int wf  = t & 3;
    const bool wAct = (BM == 32) || (t < 64);
    const int xn4 = t & 15;
    const int xkr = t >> 4;

    const int kb  = wg * (K >> 2);
    const int NIT = K >> 6;

    float4 rw, rx[2];
    float4 acc[TO];
    #pragma unroll
    for (int j = 0; j < TO; j++) acc[j] = make_float4(0.f, 0.f, 0.f, 0.f);

    if (wAct) rw = *(const float4*)&W[(o0 + wo) * 512 + kb + wf * 4];
    #pragma unroll
    for (int p = 0; p < 2; p++)
        rx[p] = *(const float4*)&X0[(kb + xkr + p * 8) * 512 + n0 + xn4 * 4];

    for (int it = 0; it < NIT; it++) {
        __syncthreads();
        if (wAct) {
            sW[wg][(wf * 4 + 0) * WS + wo] = rw.x;
            sW[wg][(wf * 4 + 1) * WS + wo] = rw.y;
            sW[wg][(wf * 4 + 2) * WS + wo] = rw.z;
            sW[wg][(wf * 4 + 3) * WS + wo] = rw.w;
        }
        #pragma unroll
        for (int p = 0; p < 2; p++)
            *(float4*)&sX[wg][(xkr + p * 8) * 68 + xn4 * 4] = rx[p];
        __syncthreads();

        if (it + 1 < NIT) {
            const int k0 = kb + (it + 1) * 16;
            if (wAct) rw = *(const float4*)&W[(o0 + wo) * 512 + k0 + wf * 4];
            #pragma unroll
            for (int p = 0; p < 2; p++)
                rx[p] = *(const float4*)&X0[(k0 + xkr + p * 8) * 512 + n0 + xn4 * 4];
        }

        #pragma unroll
        for (int k = 0; k < 16; k++) {
            float4 xv = *(const float4*)&sX[wg][k * 68 + nI * 4];
            if (TO == 4) {
                float4 wv = *(const float4*)&sW[wg][k * WS + oG * 4];
                acc[0].x += wv.x * xv.x; acc[0].y += wv.x * xv.y;
                acc[0].z += wv.x * xv.z; acc[0].w += wv.x * xv.w;
                acc[1].x += wv.y * xv.x; acc[1].y += wv.y * xv.y;
                acc[1].z += wv.y * xv.z; acc[1].w += wv.y * xv.w;
                acc[2].x += wv.z * xv.x; acc[2].y += wv.z * xv.y;
                acc[2].z += wv.z * xv.z; acc[2].w += wv.z * xv.w;
                acc[3].x += wv.w * xv.x; acc[3].y += wv.w * xv.y;
                acc[3].z += wv.w * xv.z; acc[3].w += wv.w * xv.w;
            } else {
                float2 wv = *(const float2*)&sW[wg][k * WS + oG * 2];
                acc[0].x += wv.x * xv.x; acc[0].y += wv.x * xv.y;
                acc[0].z += wv.x * xv.z; acc[0].w += wv.x * xv.w;
                acc[1].x += wv.y * xv.x; acc[1].y += wv.y * xv.y;
                acc[1].z += wv.y * xv.z; acc[1].w += wv.y * xv.w;
            }
        }
    }

    if (wg == 1) {
        #pragma unroll
        for (int j = 0; j < TO; j++) *(float4*)&sR[0][(t * TO + j) * 4] = acc[j];
    } else if (wg == 3) {
        #pragma unroll
        for (int j = 0; j < TO; j++) *(float4*)&sR[1][(t * TO + j) * 4] = acc[j];
    }
    __syncthreads();
    if (wg == 0) {
        #pragma unroll
        for (int j = 0; j < TO; j++) {
            float4 r = *(const float4*)&sR[0][(t * TO + j) * 4];
            acc[j].x += r.x; acc[j].y += r.y; acc[j].z += r.z; acc[j].w += r.w;
        }
    } else if (wg == 2) {
        #pragma unroll
        for (int j = 0; j < TO; j++) {
            float4 r = *(const float4*)&sR[1][(t * TO + j) * 4];
            acc[j].x += r.x; acc[j].y += r.y; acc[j].z += r.z; acc[j].w += r.w;
        }
    }
    __syncthreads();
    if (wg == 2) {
        #pragma unroll
        for (int j = 0; j < TO; j++) *(float4*)&sR[0][(t * TO + j) * 4] = acc[j];
    }
    __syncthreads();
    if (wg == 0) {
        #pragma unroll
        for (int j = 0; j < TO; j++) {
            float4 r = *(const float4*)&sR[0][(t * TO + j) * 4];
            const int o = o0 + oG * TO + j;
            const float b = bias ? bias[o] : 0.f;
            float4 v = acc[j];
            v.x += r.x + b; v.y += r.y + b; v.z += r.z + b; v.w += r.w + b;
            if (relu) {
                v.x = fmaxf(v.x, 0.f); v.y = fmaxf(v.y, 0.f);
                v.z = fmaxf(v.z, 0.f); v.w = fmaxf(v.w, 0.f);
            }
            *(float4*)&out[o * 512 + n0 + nI * 4] = v;
        }
    }
}

// ---------------- stage kernels ----------------

// h2pre = wa[:, :256] @ x + ba    (inputs only — runs concurrent with qk/score)
__global__ void __launch_bounds__(256) k_h2a(
    const float* __restrict__ wa, const float* __restrict__ x,
    const float* __restrict__ ba)
{
    gemm2<32>(wa, x, ba, nullptr, g_h2pre, 256, false);
}

// aq = w1[:, :D] @ x + b1 ; ak = w1[:, D:] @ src   grid (8,8,2), 256 thr
__global__ void __launch_bounds__(256) k_qk(
    const float* __restrict__ w1, const float* __restrict__ x,
    const float* __restrict__ src, const float* __restrict__ b1)
{
    if (blockIdx.z == 0)
        gemm2<32>(w1,       x,   b1,      nullptr, g_aq, 256, false);
    else
        gemm2<32>(w1 + 256, src, nullptr, nullptr, g_ak, 256, false);
}

// scores[n][m] = sum_d w2[d]*relu(aq[d][n]+ak[d][m]) + b2   grid (8,16), 256 thr
// 2 warpgroups split d (128 each), KC=32; thread tile 4n x 4m
__global__ void __launch_bounds__(256) k_score(
    const float* __restrict__ w2, const float* __restrict__ b2,
    float* __restrict__ scores)
{
    const int m0  = blockIdx.x * 64;
    const int n0  = blockIdx.y * 32;
    const int tid = threadIdx.x;
    const int wg  = tid >> 7;
    const int t   = tid & 127;
    const int mI  = t & 15;
    const int nG  = t >> 4;

    __shared__ __align__(16) float sA[2][32 * 36];
    __shared__ __align__(16) float sB[2][32 * 68];
    __shared__ float sw[2][32];
    __shared__ __align__(16) float sR[128 * 16];

    const int an4 = t & 7,  adr = t >> 3;
    const int bm4 = t & 15, bdr = t >> 4;
    const int db  = wg * 128;

    float4 ra[2], rb[4];
    float rwv;
    float4 acc[4];
    #pragma unroll
    for (int j = 0; j < 4; j++) acc[j] = make_float4(0.f, 0.f, 0.f, 0.f);

    #pragma unroll
    for (int p = 0; p < 2; p++)
        ra[p] = *(const float4*)&g_aq[(db + adr + p * 16) * 512 + n0 + an4 * 4];
    #pragma unroll
    for (int p = 0; p < 4; p++)
        rb[p] = *(const float4*)&g_ak[(db + bdr + p * 8) * 512 + m0 + bm4 * 4];
    rwv = (t < 32) ? w2[db + t] : 0.f;

    for (int it = 0; it < 4; it++) {
        __syncthreads();
        #pragma unroll
        for (int p = 0; p < 2; p++)
            *(float4*)&sA[wg][(adr + p * 16) * 36 + an4 * 4] = ra[p];
        #pragma unroll
        for (int p = 0; p < 4; p++)
            *(float4*)&sB[wg][(bdr + p * 8) * 68 + bm4 * 4] = rb[p];
        if (t < 32) sw[wg][t] = rwv;
        __syncthreads();

        if (it + 1 < 4) {
            const int d0 = db + (it + 1) * 32;
            #pragma unroll
            for (int p = 0; p < 2; p++)
                ra[p] = *(const float4*)&g_aq[(d0 + adr + p * 16) * 512 + n0 + an4 * 4];
            #pragma unroll
            for (int p = 0; p < 4; p++)
                rb[p] = *(const float4*)&g_ak[(d0 + bdr + p * 8) * 512 + m0 + bm4 * 4];
            if (t < 32) rwv = w2[d0 + t];
        }

        #pragma unroll
        for (int d = 0; d < 32; d++) {
            float4 av = *(const float4*)&sA[wg][d * 36 + nG * 4];
            float4 bv = *(const float4*)&sB[wg][d * 68 + mI * 4];
            float w  = sw[wg][d];
            float a[4] = {av.x, av.y, av.z, av.w};
            #pragma unroll
            for (int j = 0; j < 4; j++) {
                acc[j].x += w * fmaxf(a[j] + bv.x, 0.f);
                acc[j].y += w * fmaxf(a[j] + bv.y, 0.f);
                acc[j].z += w * fmaxf(a[j] + bv.z, 0.f);
                acc[j].w += w * fmaxf(a[j] + bv.w, 0.f);
            }
        }
    }

    if (wg == 1) {
        #pragma unroll
        for (int j = 0; j < 4; j++)
            *(float4*)&sR[(t * 4 + j) * 4] = acc[j];
    }
    __syncthreads();
    if (wg == 0) {
        const float bs = b2[0];
        #pragma unroll
        for (int j = 0; j < 4; j++) {
            float4 r = *(const float4*)&sR[(t * 4 + j) * 4];
            const int n = n0 + nG * 4 + j;
            float4 v = acc[j];
            v.x += r.x + bs; v.y += r.y + bs;
            v.z += r.z + bs; v.w += r.w + bs;
            *(float4*)&scores[n * 512 + m0 + mI * 4] = v;
        }
    }
}

// softmax over m per row n -> transposed prob g_probT[m][n]   grid 128 x 128
__global__ void __launch_bounds__(128) k_softmaxT(const float* __restrict__ scores)
{
    const int n0   = blockIdx.x * 4;
    const int tid  = threadIdx.x;
    const int lane = tid & 31, w = tid >> 5;
    __shared__ float sP[4][513];

    const float* row = scores + (n0 + w) * 512;
    float v[16];
    float mx = -1e30f;
    #pragma unroll
    for (int i = 0; i < 16; i++) { v[i] = row[lane + 32 * i]; mx = fmaxf(mx, v[i]); }
    #pragma unroll
    for (int o = 16; o; o >>= 1) mx = fmaxf(mx, __shfl_xor_sync(0xffffffffu, mx, o));
    float s = 0.f;
    #pragma unroll
    for (int i = 0; i < 16; i++) { v[i] = __expf(v[i] - mx); s += v[i]; }
    #pragma unroll
    for (int o = 16; o; o >>= 1) s += __shfl_xor_sync(0xffffffffu, s, o);
    float inv = 1.f / s;
    #pragma unroll
    for (int i = 0; i < 16; i++) sP[w][lane + 32 * i] = v[i] * inv;
    __syncthreads();
    #pragma unroll
    for (int i = 0; i < 4; i++) {
        int m = tid + 128 * i;
        float4 t = make_float4(sP[0][m], sP[1][m], sP[2][m], sP[3][m]);
        *(float4*)&g_probT[m * 512 + n0] = t;
    }
}

// message = src @ probT          grid (8,16), 512 thr
__global__ void __launch_bounds__(512) k_msg(const float* __restrict__ src)
{
    gemm4<16>(src, g_probT, nullptr, g_msg, 512, false);
}

// h2 = relu(h2pre + wa[:, 256:] @ msg)   grid (8,16), 256 thr
__global__ void __launch_bounds__(256) k_h2b(
    const float* __restrict__ wa)
{
    gemm2<32>(wa + 256, g_msg, nullptr, g_h2pre, g_h2, 256, true);
}

// y = wb @ h2 + bb               grid (8,16), 512 thr
__global__ void __launch_bounds__(512) k_y(
    const float* __restrict__ wb, const float* __restrict__ bb,
    float* __restrict__ y)
{
    gemm4<16>(wb, g_h2, bb, y, 512, false);
}

// ---------------- launch ----------------
extern "C" void kernel_launch(void* const* d_in, const int* in_sizes, int n_in,
                              void* d_out, int out_size)
{
    const float* x   = (const float*)d_in[0];
    const float* src = (const float*)d_in[1];
    const float* w1  = (const float*)d_in[2];
    const float* b1  = (const float*)d_in[3];
    const float* w2  = (const float*)d_in[4];
    const float* b2  = (const float*)d_in[5];
    const float* wa  = (const float*)d_in[6];
    const float* ba  = (const float*)d_in[7];
    const float* wb  = (const float*)d_in[8];
    const float* bb  = (const float*)d_in[9];

    float* y      = (float*)d_out;   // (1, D, NQ)
    float* scores = y + D * NQ;      // (1, NQ, NK)

    // fork a side stream for h2a (input-only dependency)
    cudaStream_t s1 = 0;
    cudaEvent_t eF = nullptr, eJ = nullptr;
    bool forked = (cudaStreamCreateWithFlags(&s1, cudaStreamNonBlocking) == cudaSuccess);
    if (forked) {
        cudaEventCreateWithFlags(&eF, cudaEventDisableTiming);
        cudaEventCreateWithFlags(&eJ, cudaEventDisableTiming);
        cudaEventRecord(eF, 0);
        cudaStreamWaitEvent(s1, eF, 0);
    }

    k_h2a<<<dim3(8, 16), 256, 0, forked ? s1 : 0>>>(wa, x, ba);
    if (forked) cudaEventRecord(eJ, s1);

    k_qk      <<<dim3(8, 8, 2), 256>>>(w1, x, src, b1);
    k_score   <<<dim3(8, 16),   256>>>(w2, b2, scores);
    k_softmaxT<<<128,           128>>>(scores);
    k_msg     <<<dim3(8, 16),   512>>>(src);

    if (forked) cudaStreamWaitEvent(0, eJ, 0);     // join before h2b
    k_h2b     <<<dim3(8, 16),   256>>>(wa);
    k_y       <<<dim3(8, 16),   512>>>(wb, bb, y);
    // streams/events intentionally leaked: kernel_launch is called only a few
    // times (correctness + capture); destroying during capture is illegal.
}

// round 10
// speedup vs baseline: 1.2299x; 1.2299x over previous
#include <cuda_runtime.h>
#include <math.h>

#define D   256
#define NQ  512
#define NK  512

// ---------------- scratch ----------------
__device__ __align__(16) float g_aq[D * NQ];      // (d, n)
__device__ __align__(16) float g_ak[D * NK];      // (d, m)
__device__ __align__(16) float g_probT[NK * NQ];  // (m, n)
__device__ __align__(16) float g_msg[D * NQ];     // (d, n)
__device__ __align__(16) float g_h2[2 * D * NQ];  // (o, n)

// ---------------- tf32 helpers ----------------
__device__ __forceinline__ float f2tf(float f) {
    unsigned u; asm("cvt.rna.tf32.f32 %0, %1;" : "=r"(u) : "f"(f));
    return __uint_as_float(u);
}
__device__ __forceinline__ void mma_tf32(float4& c,
    float a0, float a1, float a2, float a3, float b0, float b1)
{
    asm("mma.sync.aligned.m16n8k8.row.col.f32.tf32.tf32.f32 "
        "{%0,%1,%2,%3}, {%4,%5,%6,%7}, {%8,%9}, {%0,%1,%2,%3};"
        : "+f"(c.x), "+f"(c.y), "+f"(c.z), "+f"(c.w)
        : "r"(__float_as_uint(a0)), "r"(__float_as_uint(a1)),
          "r"(__float_as_uint(a2)), "r"(__float_as_uint(a3)),
          "r"(__float_as_uint(b0)), "r"(__float_as_uint(b1)));
}

// ---------- TF32 tensor-core GEMM: tile 32 x 64, 256 thr, 2-way split-K -----
// out[o0..o0+31][n0..n0+63] = act(sum_k W[o][k]*X[k][n] + bias[o])
// 8 warps: wg = warp>>2 owns K-half; 4 warps/wg each compute m16 x n32
// (4 m16n8k8 mma tiles). Strides 512. DUAL: X rows<256 from X0 else X1.
template<bool DUAL>
__device__ __forceinline__ void gemm_mma(
    const float* __restrict__ W, const float* __restrict__ X0,
    const float* __restrict__ X1, const float* __restrict__ bias,
    float* __restrict__ out, int K, bool relu)
{
    const int n0   = blockIdx.x * 64;
    const int o0   = blockIdx.y * 32;
    const int tid  = threadIdx.x;      // 256
    const int wg   = tid >> 7;         // K half
    const int t    = tid & 127;
    const int wq   = t >> 5;           // warp within wg
    const int lane = t & 31;
    const int g    = lane >> 2, t4 = lane & 3;
    const int mt   = wq & 1;           // m16 tile (0/1)
    const int ng   = (wq >> 1) * 32;   // n group (0/32)

    __shared__ __align__(16) float sW[2][32 * 40];  // [k][o] (tf32 bits)
    __shared__ __align__(16) float sX[2][32 * 72];  // [k][n] (tf32 bits)
    __shared__ __align__(16) float sR[4][32][16];   // split-K partials

    // loaders (within wg; layout identical to proven r5 core)
    const int wo  = t >> 2, wf = t & 3;   // W: 2 float4 per thread
    const int xn4 = t & 15, xkr = t >> 4; // X: 4 float4 per thread

    const int kb  = wg * (K >> 1);
    const int NIT = K >> 6;               // (K/2)/32

    float4 rw[2], rx[4];
    float4 acc[4];
    #pragma unroll
    for (int j = 0; j < 4; j++) acc[j] = make_float4(0.f, 0.f, 0.f, 0.f);

    {   // prefetch tile 0
        const int k0 = kb;
        #pragma unroll
        for (int p = 0; p < 2; p++)
            rw[p] = *(const float4*)&W[(o0 + wo) * 512 + k0 + (wf + p * 4) * 4];
        const float* Xb = (!DUAL || k0 < 256) ? X0 + k0 * 512
                                              : X1 + (k0 - 256) * 512;
        #pragma unroll
        for (int p = 0; p < 4; p++)
            rx[p] = *(const float4*)&Xb[(xkr + p * 8) * 512 + n0 + xn4 * 4];
    }

    for (int it = 0; it < NIT; it++) {
        __syncthreads();
        #pragma unroll
        for (int p = 0; p < 2; p++) {
            const int kB = (wf + p * 4) * 4;
            sW[wg][(kB + 0) * 40 + wo] = f2tf(rw[p].x);
            sW[wg][(kB + 1) * 40 + wo] = f2tf(rw[p].y);
            sW[wg][(kB + 2) * 40 + wo] = f2tf(rw[p].z);
            sW[wg][(kB + 3) * 40 + wo] = f2tf(rw[p].w);
        }
        #pragma unroll
        for (int p = 0; p < 4; p++) {
            float4 c = make_float4(f2tf(rx[p].x), f2tf(rx[p].y),
                                   f2tf(rx[p].z), f2tf(rx[p].w));
            *(float4*)&sX[wg][(xkr + p * 8) * 72 + xn4 * 4] = c;
        }
        __syncthreads();

        if (it + 1 < NIT) {            // prefetch next tile (overlaps compute)
            const int k0 = kb + (it + 1) * 32;
            #pragma unroll
            for (int p = 0; p < 2; p++)
                rw[p] = *(const float4*)&W[(o0 + wo) * 512 + k0 + (wf + p * 4) * 4];
            const float* Xb = (!DUAL || k0 < 256) ? X0 + k0 * 512
                                                  : X1 + (k0 - 256) * 512;
            #pragma unroll
            for (int p = 0; p < 4; p++)
                rx[p] = *(const float4*)&Xb[(xkr + p * 8) * 512 + n0 + xn4 * 4];
        }

        // 4 k8 steps
        #pragma unroll
        for (int s = 0; s < 4; s++) {
            const int ks = s * 8;
            const int ob = mt * 16 + g;
            float a0 = sW[wg][(ks + t4) * 40 + ob];
            float a1 = sW[wg][(ks + t4) * 40 + ob + 8];
            float a2 = sW[wg][(ks + t4 + 4) * 40 + ob];
            float a3 = sW[wg][(ks + t4 + 4) * 40 + ob + 8];
            #pragma unroll
            for (int j = 0; j < 4; j++) {
                const int nc = ng + j * 8 + g;
                float b0 = sX[wg][(ks + t4) * 72 + nc];
                float b1 = sX[wg][(ks + t4 + 4) * 72 + nc];
                mma_tf32(acc[j], a0, a1, a2, a3, b0, b1);
            }
        }
    }

    // split-K reduce + epilogue
    if (wg == 1) {
        #pragma unroll
        for (int j = 0; j < 4; j++) *(float4*)&sR[wq][lane][j * 4] = acc[j];
    }
    __syncthreads();
    if (wg == 0) {
        const int oA = o0 + mt * 16 + g;
        const int oB = oA + 8;
        const float bA = bias ? bias[oA] : 0.f;
        const float bB = bias ? bias[oB] : 0.f;
        #pragma unroll
        for (int j = 0; j < 4; j++) {
            float4 r = *(const float4*)&sR[wq][lane][j * 4];
            float c0 = acc[j].x + r.x + bA;
            float c1 = acc[j].y + r.y + bA;
            float c2 = acc[j].z + r.z + bB;
            float c3 = acc[j].w + r.w + bB;
            if (relu) {
                c0 = fmaxf(c0, 0.f); c1 = fmaxf(c1, 0.f);
                c2 = fmaxf(c2, 0.f); c3 = fmaxf(c3, 0.f);
            }
            const int nc = n0 + ng + j * 8 + 2 * t4;
            *(float2*)&out[oA * 512 + nc] = make_float2(c0, c1);
            *(float2*)&out[oB * 512 + nc] = make_float2(c2, c3);
        }
    }
}

// ---------------- stage kernels ----------------

// aq = w1[:, :D] @ x + b1 ; ak = w1[:, D:] @ src   grid (8,8,2), 256 thr
__global__ void __launch_bounds__(256) k_qk(
    const float* __restrict__ w1, const float* __restrict__ x,
    const float* __restrict__ src, const float* __restrict__ b1)
{
    if (blockIdx.z == 0)
        gemm_mma<false>(w1,       x,   nullptr, b1,      g_aq, 256, false);
    else
        gemm_mma<false>(w1 + 256, src, nullptr, nullptr, g_ak, 256, false);
}

// scores[n][m] = sum_d w2[d]*relu(aq[d][n]+ak[d][m]) + b2   grid (8,16), 256 thr
// (unchanged proven r5 SIMT kernel: 2 warpgroups split d, KC=32, 4n x 4m tile)
__global__ void __launch_bounds__(256) k_score(
    const float* __restrict__ w2, const float* __restrict__ b2,
    float* __restrict__ scores)
{
    const int m0  = blockIdx.x * 64;
    const int n0  = blockIdx.y * 32;
    const int tid = threadIdx.x;
    const int wg  = tid >> 7;
    const int t   = tid & 127;
    const int mI  = t & 15;
    const int nG  = t >> 4;

    __shared__ __align__(16) float sA[2][32 * 36];
    __shared__ __align__(16) float sB[2][32 * 68];
    __shared__ float sw[2][32];
    __shared__ __align__(16) float sR[128 * 16];

    const int an4 = t & 7,  adr = t >> 3;
    const int bm4 = t & 15, bdr = t >> 4;
    const int db  = wg * 128;

    float4 ra[2], rb[4];
    float rwv;
    float4 acc[4];
    #pragma unroll
    for (int j = 0; j < 4; j++) acc[j] = make_float4(0.f, 0.f, 0.f, 0.f);

    #pragma unroll
    for (int p = 0; p < 2; p++)
        ra[p] = *(const float4*)&g_aq[(db + adr + p * 16) * 512 + n0 + an4 * 4];
    #pragma unroll
    for (int p = 0; p < 4; p++)
        rb[p] = *(const float4*)&g_ak[(db + bdr + p * 8) * 512 + m0 + bm4 * 4];
    rwv = (t < 32) ? w2[db + t] : 0.f;

    for (int it = 0; it < 4; it++) {
        __syncthreads();
        #pragma unroll
        for (int p = 0; p < 2; p++)
            *(float4*)&sA[wg][(adr + p * 16) * 36 + an4 * 4] = ra[p];
        #pragma unroll
        for (int p = 0; p < 4; p++)
            *(float4*)&sB[wg][(bdr + p * 8) * 68 + bm4 * 4] = rb[p];
        if (t < 32) sw[wg][t] = rwv;
        __syncthreads();

        if (it + 1 < 4) {
            const int d0 = db + (it + 1) * 32;
            #pragma unroll
            for (int p = 0; p < 2; p++)
                ra[p] = *(const float4*)&g_aq[(d0 + adr + p * 16) * 512 + n0 + an4 * 4];
            #pragma unroll
            for (int p = 0; p < 4; p++)
                rb[p] = *(const float4*)&g_ak[(d0 + bdr + p * 8) * 512 + m0 + bm4 * 4];
            if (t < 32) rwv = w2[d0 + t];
        }

        #pragma unroll
        for (int d = 0; d < 32; d++) {
            float4 av = *(const float4*)&sA[wg][d * 36 + nG * 4];
            float4 bv = *(const float4*)&sB[wg][d * 68 + mI * 4];
            float w  = sw[wg][d];
            float a[4] = {av.x, av.y, av.z, av.w};
            #pragma unroll
            for (int j = 0; j < 4; j++) {
                acc[j].x += w * fmaxf(a[j] + bv.x, 0.f);
                acc[j].y += w * fmaxf(a[j] + bv.y, 0.f);
                acc[j].z += w * fmaxf(a[j] + bv.z, 0.f);
                acc[j].w += w * fmaxf(a[j] + bv.w, 0.f);
            }
        }
    }

    if (wg == 1) {
        #pragma unroll
        for (int j = 0; j < 4; j++)
            *(float4*)&sR[(t * 4 + j) * 4] = acc[j];
    }
    __syncthreads();
    if (wg == 0) {
        const float bs = b2[0];
        #pragma unroll
        for (int j = 0; j < 4; j++) {
            float4 r = *(const float4*)&sR[(t * 4 + j) * 4];
            const int n = n0 + nG * 4 + j;
            float4 v = acc[j];
            v.x += r.x + bs; v.y += r.y + bs;
            v.z += r.z + bs; v.w += r.w + bs;
            *(float4*)&scores[n * 512 + m0 + mI * 4] = v;
        }
    }
}

// softmax over m per row n -> transposed prob. 128 blocks x 256 thr,
// 2 warps per row (latency halved vs 1-warp-per-row version).
__global__ void __launch_bounds__(256) k_softmaxT(const float* __restrict__ scores)
{
    const int n0   = blockIdx.x * 4;
    const int tid  = threadIdx.x;
    const int w    = tid >> 5, lane = tid & 31;
    const int r    = w >> 1, h = w & 1;
    __shared__ float sP[4][516];
    __shared__ float sred[8];

    const float* row = scores + (n0 + r) * 512 + h * 256;
    float v[8];
    float mx = -1e30f;
    #pragma unroll
    for (int i = 0; i < 8; i++) { v[i] = row[lane + 32 * i]; mx = fmaxf(mx, v[i]); }
    #pragma unroll
    for (int o = 16; o; o >>= 1) mx = fmaxf(mx, __shfl_xor_sync(0xffffffffu, mx, o));
    if (lane == 0) sred[w] = mx;
    __syncthreads();
    const float m = fmaxf(sred[r * 2], sred[r * 2 + 1]);
    float s = 0.f;
    #pragma unroll
    for (int i = 0; i < 8; i++) { v[i] = __expf(v[i] - m); s += v[i]; }
    #pragma unroll
    for (int o = 16; o; o >>= 1) s += __shfl_xor_sync(0xffffffffu, s, o);
    __syncthreads();
    if (lane == 0) sred[w] = s;
    __syncthreads();
    const float inv = 1.f / (sred[r * 2] + sred[r * 2 + 1]);
    #pragma unroll
    for (int i = 0; i < 8; i++) sP[r][h * 256 + lane + 32 * i] = v[i] * inv;
    __syncthreads();
    #pragma unroll
    for (int i = 0; i < 2; i++) {
        int mi = tid + 256 * i;
        float4 tv = make_float4(sP[0][mi], sP[1][mi], sP[2][mi], sP[3][mi]);
        *(float4*)&g_probT[mi * 512 + n0] = tv;
    }
}

// message = src @ probT          grid (8,8), 256 thr
__global__ void __launch_bounds__(256) k_msg(const float* __restrict__ src)
{
    gemm_mma<false>(src, g_probT, nullptr, nullptr, g_msg, 512, false);
}

// h2 = relu(wa @ [x; msg] + ba)  grid (8,16), 256 thr
__global__ void __launch_bounds__(256) k_h2(
    const float* __restrict__ wa, const float* __restrict__ x,
    const float* __restrict__ ba)
{
    gemm_mma<true>(wa, x, g_msg, ba, g_h2, 512, true);
}

// y = wb @ h2 + bb               grid (8,8), 256 thr
__global__ void __launch_bounds__(256) k_y(
    const float* __restrict__ wb, const float* __restrict__ bb,
    float* __restrict__ y)
{
    gemm_mma<false>(wb, g_h2, nullptr, bb, y, 512, false);
}

// ---------------- launch ----------------
extern "C" void kernel_launch(void* const* d_in, const int* in_sizes, int n_in,
                              void* d_out, int out_size)
{
    const float* x   = (const float*)d_in[0];
    const float* src = (const float*)d_in[1];
    const float* w1  = (const float*)d_in[2];
    const float* b1  = (const float*)d_in[3];
    const float* w2  = (const float*)d_in[4];
    const float* b2  = (const float*)d_in[5];
    const float* wa  = (const float*)d_in[6];
    const float* ba  = (const float*)d_in[7];
    const float* wb  = (const float*)d_in[8];
    const float* bb  = (const float*)d_in[9];

    float* y      = (float*)d_out;   // (1, D, NQ)
    float* scores = y + D * NQ;      // (1, NQ, NK)

    k_qk      <<<dim3(8, 8, 2), 256>>>(w1, x, src, b1);
    k_score   <<<dim3(8, 16),   256>>>(w2, b2, scores);
    k_softmaxT<<<128,           256>>>(scores);
    k_msg     <<<dim3(8, 8),    256>>>(src);
    k_h2      <<<dim3(8, 16),   256>>>(wa, x, ba);
    k_y       <<<dim3(8, 8),    256>>>(wb, bb, y);
}